// round 1
// baseline (speedup 1.0000x reference)
#include <cuda_runtime.h>
#include <cstdint>
#include <cstdio>

#define TT 2048
#define DD 2048
#define HDIM 1024
#define KTAG 22
#define ENDT 20
#define STARTT 21
#define NEGV -10000.0f
#define NBLK 148
#define NBPD 74   /* persistent blocks per direction */

// ---------------- scratch (device globals: allocation-free) ----------------
__device__ float g_G[2u * TT * 4096u];        // input gates, permuted [dir][t][unit*4+gate]
__device__ float g_lstm[(size_t)TT * 2048u];  // concat hidden states [t][dir*1024+unit]
__device__ float g_feats[TT * KTAG];
__device__ float g_h[2][2048];                // double-buffered h state [parity][dir*1024+unit]
__device__ unsigned g_count;                  // grid barrier counter

// ---------------- init: reset barrier, load h0 ----------------
__global__ void init_kernel(const float* __restrict__ h0) {
    int i = blockIdx.x * blockDim.x + threadIdx.x;
    if (i < 2048) g_h[0][i] = h0[i];
    if (i == 0) g_count = 0u;
}

// ---------------- SGEMM: G = X @ W^T + bias (both dirs, permuted cols) ----------------
#define BM 128
#define BN 128
#define BKK 8
#define PADG 136

__global__ void __launch_bounds__(256) gemm_kernel(
    const float* __restrict__ X,
    const float* __restrict__ Wf, const float* __restrict__ Wr,
    const float* __restrict__ bihf, const float* __restrict__ bhhf,
    const float* __restrict__ bihr, const float* __restrict__ bhhr)
{
    __shared__ __align__(16) float As[2][BKK][PADG];
    __shared__ __align__(16) float Bs[2][BKK][PADG];

    int tid = threadIdx.x;
    int m0 = blockIdx.y * BM;
    int n0 = blockIdx.x * BN;
    int dir = n0 >> 12;                       // 4096 cols per direction
    const float* Wd  = dir ? Wr   : Wf;
    const float* bih = dir ? bihr : bihf;
    const float* bhh = dir ? bhhr : bhhf;

    int rid = tid >> 1;                       // 0..127
    int kk  = (tid & 1) * 4;
    const float* aptr = X + (size_t)(m0 + rid) * DD + kk;
    int n  = n0 + rid;
    int wl = (n & 3) * HDIM + ((n & 4095) >> 2);   // permuted W row
    const float* bptr = Wd + (size_t)wl * DD + kk;

    int tx = tid & 15, ty = tid >> 4;
    float c[8][8];
#pragma unroll
    for (int i = 0; i < 8; i++)
#pragma unroll
        for (int j = 0; j < 8; j++) c[i][j] = 0.f;

    float4 a  = *(const float4*)aptr;
    float4 bv = *(const float4*)bptr;
#pragma unroll
    for (int j = 0; j < 4; j++) {
        As[0][kk + j][rid] = ((const float*)&a)[j];
        Bs[0][kk + j][rid] = ((const float*)&bv)[j];
    }
    __syncthreads();

    const int nk = DD / BKK;
    for (int kb = 0; kb < nk; kb++) {
        int p = kb & 1;
        if (kb + 1 < nk) {
            a  = *(const float4*)(aptr + (size_t)(kb + 1) * BKK);
            bv = *(const float4*)(bptr + (size_t)(kb + 1) * BKK);
        }
#pragma unroll
        for (int k = 0; k < BKK; k++) {
            float4 a0 = *(const float4*)&As[p][k][ty * 8];
            float4 a1 = *(const float4*)&As[p][k][ty * 8 + 4];
            float4 b0 = *(const float4*)&Bs[p][k][tx * 8];
            float4 b1 = *(const float4*)&Bs[p][k][tx * 8 + 4];
            float av[8] = {a0.x, a0.y, a0.z, a0.w, a1.x, a1.y, a1.z, a1.w};
            float bw[8] = {b0.x, b0.y, b0.z, b0.w, b1.x, b1.y, b1.z, b1.w};
#pragma unroll
            for (int i = 0; i < 8; i++)
#pragma unroll
                for (int j = 0; j < 8; j++) c[i][j] += av[i] * bw[j];
        }
        if (kb + 1 < nk) {
            int q = 1 - p;
#pragma unroll
            for (int j = 0; j < 4; j++) {
                As[q][kk + j][rid] = ((const float*)&a)[j];
                Bs[q][kk + j][rid] = ((const float*)&bv)[j];
            }
        }
        __syncthreads();
    }

    // epilogue: bias (per permuted col) + store
    float bb[8];
#pragma unroll
    for (int j = 0; j < 8; j++) {
        int nn  = n0 + tx * 8 + j;
        int wl2 = (nn & 3) * HDIM + ((nn & 4095) >> 2);
        bb[j] = __ldg(&bih[wl2]) + __ldg(&bhh[wl2]);
    }
    size_t dbase = (size_t)dir * TT * 4096u;
#pragma unroll
    for (int i = 0; i < 8; i++) {
        int m = m0 + ty * 8 + i;
        float* orow = g_G + dbase + (size_t)m * 4096u + ((n0 & 4095) + tx * 8);
        float4 o0 = {c[i][0] + bb[0], c[i][1] + bb[1], c[i][2] + bb[2], c[i][3] + bb[3]};
        float4 o1 = {c[i][4] + bb[4], c[i][5] + bb[5], c[i][6] + bb[6], c[i][7] + bb[7]};
        *(float4*)orow       = o0;
        *(float4*)(orow + 4) = o1;
    }
}

// ---------------- persistent bidirectional LSTM recurrence ----------------
// 148 CTAs (one wave), weights staged in ~229KB smem, custom grid barrier.
__global__ void __launch_bounds__(256, 1) recur_kernel(
    const float* __restrict__ Whh_f, const float* __restrict__ Whh_r,
    const float* __restrict__ c0)
{
    extern __shared__ __align__(16) float sm[];
    float* ws  = sm;            // up to 14*4*1024 = 57344 floats
    float* gs  = sm + 57344;    // 56 recurrent dot results
    float* gv  = gs + 56;       // 56 input-gate values
    float* cst = gv + 56;       // 16 cell states

    int b   = blockIdx.x;
    int dir = (b >= NBPD) ? 1 : 0;
    int lb  = dir ? b - NBPD : b;
    int u0  = (lb * HDIM) / NBPD;
    int u1  = ((lb + 1) * HDIM) / NBPD;
    int cnt = u1 - u0;
    int nr  = cnt * 4;
    int tid = threadIdx.x, lane = tid & 31, wid = tid >> 5;
    const float* Whh = dir ? Whh_r : Whh_f;

    // stage this block's Whh rows into smem (rows: local_unit*4 + gate)
    for (int r = 0; r < nr; r++) {
        int gate = r & 3, lu = r >> 2;
        const float4* src = (const float4*)(Whh + (size_t)(gate * HDIM + u0 + lu) * HDIM);
        ((float4*)(ws + r * HDIM))[tid] = src[tid];
    }
    if (tid < cnt) cst[tid] = c0[dir * HDIM + u0 + tid];
    __syncthreads();

    const float* Gbase = g_G + (size_t)dir * TT * 4096u + (size_t)u0 * 4u;

    for (int s = 0; s < TT; s++) {
        int tg = dir ? (TT - 1 - s) : s;
        float gvr = 0.f;
        if (tid < nr) gvr = __ldg(Gbase + (size_t)tg * 4096u + tid);

        // load h (this direction) into regs; ldcg bypasses stale L1
        const float* hsrc = g_h[s & 1] + dir * HDIM;
        float hr[32];
#pragma unroll
        for (int j = 0; j < 8; j++) {
            float4 v = __ldcg((const float4*)(hsrc + lane * 4 + j * 128));
            hr[4 * j] = v.x; hr[4 * j + 1] = v.y; hr[4 * j + 2] = v.z; hr[4 * j + 3] = v.w;
        }

        // recurrent dots: warp per row, lane covers k = 4*lane + 128*j (conflict-free LDS.128)
        for (int r = wid; r < nr; r += 8) {
            const float* wrow = ws + r * HDIM;
            float acc = 0.f;
#pragma unroll
            for (int j = 0; j < 8; j++) {
                float4 w = *(const float4*)(wrow + lane * 4 + j * 128);
                acc += w.x * hr[4 * j] + w.y * hr[4 * j + 1] + w.z * hr[4 * j + 2] + w.w * hr[4 * j + 3];
            }
#pragma unroll
            for (int off = 16; off; off >>= 1) acc += __shfl_xor_sync(0xffffffffu, acc, off);
            if (lane == 0) gs[r] = acc;
        }
        if (tid < nr) gv[tid] = gvr;
        __syncthreads();

        if (tid < cnt) {
            float gi = gs[4 * tid + 0] + gv[4 * tid + 0];
            float gf = gs[4 * tid + 1] + gv[4 * tid + 1];
            float gg = gs[4 * tid + 2] + gv[4 * tid + 2];
            float go = gs[4 * tid + 3] + gv[4 * tid + 3];
            float iv = 1.f / (1.f + expf(-gi));
            float fv = 1.f / (1.f + expf(-gf));
            float gt = tanhf(gg);
            float ov = 1.f / (1.f + expf(-go));
            float cc = fv * cst[tid] + iv * gt;
            cst[tid] = cc;
            float h = ov * tanhf(cc);
            int gu = dir * HDIM + u0 + tid;
            g_h[(s + 1) & 1][gu] = h;
            int trow = dir ? (TT - 1 - s) : s;
            g_lstm[(size_t)trow * 2048u + gu] = h;
            __threadfence();
        }
        __syncthreads();

        if (tid == 0) {
            atomicAdd(&g_count, 1u);
            unsigned tgt = (unsigned)NBLK * (unsigned)(s + 1);
            while (*((volatile unsigned*)&g_count) < tgt) { }
            __threadfence();
        }
        __syncthreads();
    }
}

// ---------------- feats = lstm_out @ W_tag^T + b_tag (deterministic reduction) ----------------
__global__ void __launch_bounds__(256) feats_kernel(
    const float* __restrict__ Wt, const float* __restrict__ bt)
{
    int t = blockIdx.x, tid = threadIdx.x;
    int lane = tid & 31, wid = tid >> 5;
    __shared__ float red2[KTAG][8];

    const float* row = g_lstm + (size_t)t * 2048u + tid * 8;
    float4 x0 = __ldg((const float4*)row);
    float4 x1 = __ldg((const float4*)(row + 4));

    for (int tag = 0; tag < KTAG; tag++) {
        const float* w = Wt + (size_t)tag * 2048u + tid * 8;
        float4 w0 = __ldg((const float4*)w);
        float4 w1 = __ldg((const float4*)(w + 4));
        float p = x0.x * w0.x + x0.y * w0.y + x0.z * w0.z + x0.w * w0.w
                + x1.x * w1.x + x1.y * w1.y + x1.z * w1.z + x1.w * w1.w;
#pragma unroll
        for (int off = 16; off; off >>= 1) p += __shfl_xor_sync(0xffffffffu, p, off);
        if (lane == 0) red2[tag][wid] = p;
    }
    __syncthreads();
    if (tid < KTAG) {
        float s = 0.f;
#pragma unroll
        for (int w2 = 0; w2 < 8; w2++) s += red2[tid][w2];
        g_feats[t * KTAG + tid] = s + __ldg(&bt[tid]);
    }
}

// ---------------- Viterbi DP + backtrack (single warp) ----------------
__global__ void viterbi_kernel(const float* __restrict__ trans, float* out, int out_size)
{
    extern __shared__ __align__(16) char vsm[];
    float* str  = (float*)vsm;               // 22*22 transitions
    float* fvs  = str + KTAG * KTAG;         // 22
    float* fbuf = fvs + KTAG;                // 2 * 64 * 22 feats double buffer
    unsigned char* bp = (unsigned char*)(fbuf + 2 * 64 * KTAG);  // 2048*22 backpointers

    int lane = threadIdx.x;
    for (int i = lane; i < KTAG * KTAG; i += 32) str[i] = __ldg(&trans[i]);
    if (lane < KTAG) fvs[lane] = (lane == STARTT) ? 0.f : NEGV;
    for (int i = lane; i < 64 * KTAG; i += 32) fbuf[i] = __ldg(&g_feats[i]);
    __syncwarp();

    const int CH = 64, NC = TT / CH;  // 32 chunks, 64*22 = 1408 = 44*32 floats each
    for (int c2 = 0; c2 < NC; c2++) {
        float pf[44];
        if (c2 + 1 < NC) {
#pragma unroll
            for (int i = 0; i < 44; i++)
                pf[i] = __ldg(&g_feats[(c2 + 1) * CH * KTAG + lane + i * 32]);
        }
        float* cur = fbuf + (c2 & 1) * CH * KTAG;
        for (int tt2 = 0; tt2 < CH; tt2++) {
            int t = c2 * CH + tt2;
            float nf = 0.f;
            if (lane < KTAG) {
                float m = -3.4e38f; int bi = 0;
                const float* trow = str + lane * KTAG;
                for (int p2 = 0; p2 < KTAG; p2++) {
                    float v = trow[p2] + fvs[p2];
                    if (v > m) { m = v; bi = p2; }   // strict > : first max (jnp.argmax)
                }
                nf = m + cur[tt2 * KTAG + lane];
                bp[t * KTAG + lane] = (unsigned char)bi;
            }
            __syncwarp();
            if (lane < KTAG) fvs[lane] = nf;
            __syncwarp();
        }
        if (c2 + 1 < NC) {
#pragma unroll
            for (int i = 0; i < 44; i++)
                fbuf[((c2 + 1) & 1) * CH * KTAG + lane + i * 32] = pf[i];
        }
        __syncwarp();
    }

    // terminal: max / first-index argmax of fvs + trans[END]
    float tv = (lane < KTAG) ? fvs[lane] + str[ENDT * KTAG + lane] : -3.4e38f;
    int ti = lane;
#pragma unroll
    for (int off = 16; off; off >>= 1) {
        float ov = __shfl_down_sync(0xffffffffu, tv, off);
        int   oi = __shfl_down_sync(0xffffffffu, ti, off);
        if (ov > tv || (ov == tv && oi < ti)) { tv = ov; ti = oi; }
    }
    if (lane == 0) {
        float* po = out;
        int n_path = 0;
        if (out_size >= TT + 1)      { out[0] = tv; po = out + 1; n_path = TT; }
        else if (out_size == TT)     { po = out;    n_path = TT; }
        else if (out_size >= 1)      { out[0] = tv; po = out + 1; n_path = out_size - 1; }
        int cur2 = ti;
        for (int t = TT - 1; t >= 0; t--) {
            if (t < n_path) po[t] = (float)cur2;
            cur2 = bp[t * KTAG + cur2];
        }
    }
}

// ---------------- launcher ----------------
extern "C" void kernel_launch(void* const* d_in, const int* in_sizes, int n_in,
                              void* d_out, int out_size)
{
    const float* seq    = (const float*)d_in[0];
    const float* h0     = (const float*)d_in[1];
    const float* c0     = (const float*)d_in[2];
    const float* Wih_f  = (const float*)d_in[3];
    const float* Whh_f  = (const float*)d_in[4];
    const float* bih_f  = (const float*)d_in[5];
    const float* bhh_f  = (const float*)d_in[6];
    const float* Wih_r  = (const float*)d_in[7];
    const float* Whh_r  = (const float*)d_in[8];
    const float* bih_r  = (const float*)d_in[9];
    const float* bhh_r  = (const float*)d_in[10];
    const float* W_tag  = (const float*)d_in[11];
    const float* b_tag  = (const float*)d_in[12];
    const float* transp = (const float*)d_in[13];

    static int attr_done = 0;
    const int RECUR_SMEM = (57344 + 56 + 56 + 16) * 4;             // 229,888 B
    const int VIT_SMEM   = KTAG * KTAG * 4 + KTAG * 4 + 2 * 64 * KTAG * 4 + TT * KTAG; // ~58.4 KB
    if (!attr_done) {
        cudaFuncSetAttribute(recur_kernel, cudaFuncAttributeMaxDynamicSharedMemorySize, RECUR_SMEM);
        cudaFuncSetAttribute(viterbi_kernel, cudaFuncAttributeMaxDynamicSharedMemorySize, VIT_SMEM);
        attr_done = 1;
    }

    init_kernel<<<2, 1024>>>(h0);

    dim3 ggrid(8192 / BN, 2048 / BM);
    gemm_kernel<<<ggrid, 256>>>(seq, Wih_f, Wih_r, bih_f, bhh_f, bih_r, bhh_r);

    recur_kernel<<<NBLK, 256, RECUR_SMEM>>>(Whh_f, Whh_r, c0);

    feats_kernel<<<TT, 256>>>(W_tag, b_tag);

    viterbi_kernel<<<1, 32, VIT_SMEM>>>(transp, (float*)d_out, out_size);
}

// round 2
// speedup vs baseline: 1.4129x; 1.4129x over previous
#include <cuda_runtime.h>
#include <cstdint>
#include <cstdio>

#define TT 2048
#define DD 2048
#define HDIM 1024
#define KTAG 22
#define ENDT 20
#define STARTT 21
#define NEGV -10000.0f
#define NBLK 148
#define NBPD 74   /* persistent blocks per direction */

typedef unsigned long long ull;

// ---- packed fp32x2 helpers (sm_103a dual-FMA) ----
__device__ __forceinline__ void pk2(ull& d, float x, float y) {
    asm("mov.b64 %0, {%1, %2};" : "=l"(d) : "r"(__float_as_uint(x)), "r"(__float_as_uint(y)));
}
__device__ __forceinline__ void upk2(float& x, float& y, ull d) {
    unsigned lo, hi;
    asm("mov.b64 {%0, %1}, %2;" : "=r"(lo), "=r"(hi) : "l"(d));
    x = __uint_as_float(lo); y = __uint_as_float(hi);
}
__device__ __forceinline__ void fma2(ull& d, ull a, ull b, ull c) {
    asm("fma.rn.f32x2 %0, %1, %2, %3;" : "=l"(d) : "l"(a), "l"(b), "l"(c));
}

// ---------------- scratch (device globals: allocation-free) ----------------
__device__ float g_G[2u * TT * 4096u];        // input gates, permuted [dir][t][unit*4+gate]
__device__ float g_lstm[(size_t)TT * 2048u];  // concat hidden states [t][dir*1024+unit]
__device__ float g_feats[TT * KTAG];
__device__ float g_h0[2 * HDIM];              // initial hidden state
__device__ unsigned g_cnt[2 * TT];            // per-dir per-step producer counters

// ---------------- init: reset counters, load h0 ----------------
__global__ void init_kernel(const float* __restrict__ h0) {
    int i = blockIdx.x * blockDim.x + threadIdx.x;
    if (i < 2 * HDIM) g_h0[i] = h0[i];
    if (i < 2 * TT) g_cnt[i] = 0u;
}

// ---------------- SGEMM: G = X @ W^T + bias (both dirs, permuted cols) ----------------
#define BM 128
#define BN 128
#define BKK 8
#define PADG 136

__global__ void __launch_bounds__(256) gemm_kernel(
    const float* __restrict__ X,
    const float* __restrict__ Wf, const float* __restrict__ Wr,
    const float* __restrict__ bihf, const float* __restrict__ bhhf,
    const float* __restrict__ bihr, const float* __restrict__ bhhr)
{
    __shared__ __align__(16) float As[2][BKK][PADG];
    __shared__ __align__(16) float Bs[2][BKK][PADG];

    int tid = threadIdx.x;
    int m0 = blockIdx.y * BM;
    int n0 = blockIdx.x * BN;
    int dir = n0 >> 12;                       // 4096 cols per direction
    const float* Wd  = dir ? Wr   : Wf;
    const float* bih = dir ? bihr : bihf;
    const float* bhh = dir ? bhhr : bhhf;

    int rid = tid >> 1;                       // 0..127
    int kk  = (tid & 1) * 4;
    const float* aptr = X + (size_t)(m0 + rid) * DD + kk;
    int n  = n0 + rid;
    int wl = (n & 3) * HDIM + ((n & 4095) >> 2);   // permuted W row
    const float* bptr = Wd + (size_t)wl * DD + kk;

    int tx = tid & 15, ty = tid >> 4;
    ull c2[8][4];
#pragma unroll
    for (int i = 0; i < 8; i++)
#pragma unroll
        for (int j = 0; j < 4; j++) c2[i][j] = 0ull;

    float4 a  = *(const float4*)aptr;
    float4 bv = *(const float4*)bptr;
#pragma unroll
    for (int j = 0; j < 4; j++) {
        As[0][kk + j][rid] = ((const float*)&a)[j];
        Bs[0][kk + j][rid] = ((const float*)&bv)[j];
    }
    __syncthreads();

    const int nk = DD / BKK;
    for (int kb = 0; kb < nk; kb++) {
        int p = kb & 1;
        if (kb + 1 < nk) {
            a  = *(const float4*)(aptr + (size_t)(kb + 1) * BKK);
            bv = *(const float4*)(bptr + (size_t)(kb + 1) * BKK);
        }
#pragma unroll
        for (int k = 0; k < BKK; k++) {
            float4 a0 = *(const float4*)&As[p][k][ty * 8];
            float4 a1 = *(const float4*)&As[p][k][ty * 8 + 4];
            float4 b0 = *(const float4*)&Bs[p][k][tx * 8];
            float4 b1 = *(const float4*)&Bs[p][k][tx * 8 + 4];
            ull bp0, bp1, bp2, bp3;
            pk2(bp0, b0.x, b0.y); pk2(bp1, b0.z, b0.w);
            pk2(bp2, b1.x, b1.y); pk2(bp3, b1.z, b1.w);
            float av[8] = {a0.x, a0.y, a0.z, a0.w, a1.x, a1.y, a1.z, a1.w};
#pragma unroll
            for (int i = 0; i < 8; i++) {
                ull ad; pk2(ad, av[i], av[i]);
                fma2(c2[i][0], ad, bp0, c2[i][0]);
                fma2(c2[i][1], ad, bp1, c2[i][1]);
                fma2(c2[i][2], ad, bp2, c2[i][2]);
                fma2(c2[i][3], ad, bp3, c2[i][3]);
            }
        }
        if (kb + 1 < nk) {
            int q = 1 - p;
#pragma unroll
            for (int j = 0; j < 4; j++) {
                As[q][kk + j][rid] = ((const float*)&a)[j];
                Bs[q][kk + j][rid] = ((const float*)&bv)[j];
            }
        }
        __syncthreads();
    }

    // epilogue: bias (per permuted col) + store
    float bb[8];
#pragma unroll
    for (int j = 0; j < 8; j++) {
        int nn  = n0 + tx * 8 + j;
        int wl2 = (nn & 3) * HDIM + ((nn & 4095) >> 2);
        bb[j] = __ldg(&bih[wl2]) + __ldg(&bhh[wl2]);
    }
    size_t dbase = (size_t)dir * TT * 4096u;
#pragma unroll
    for (int i = 0; i < 8; i++) {
        int m = m0 + ty * 8 + i;
        float cc[8];
#pragma unroll
        for (int j = 0; j < 4; j++) upk2(cc[2 * j], cc[2 * j + 1], c2[i][j]);
        float* orow = g_G + dbase + (size_t)m * 4096u + ((n0 & 4095) + tx * 8);
        float4 o0 = {cc[0] + bb[0], cc[1] + bb[1], cc[2] + bb[2], cc[3] + bb[3]};
        float4 o1 = {cc[4] + bb[4], cc[5] + bb[5], cc[6] + bb[6], cc[7] + bb[7]};
        *(float4*)orow       = o0;
        *(float4*)(orow + 4) = o1;
    }
}

// ---------------- persistent bidirectional LSTM recurrence v2 ----------------
// 148 CTAs (one wave, 74/dir). Per warp: 7 gate-rows; rows q<4 weights in
// REGISTERS (f32x2-packed), rows q>=4 in smem. Sync = per-step monotonic
// counters; h lives directly in g_lstm (single store).
#define QR 4   /* rows per warp kept in registers */

__global__ void __launch_bounds__(256, 1) recur_kernel(
    const float* __restrict__ Whh_f, const float* __restrict__ Whh_r,
    const float* __restrict__ c0)
{
    extern __shared__ __align__(16) float sm[];
    float* ws    = sm;                 // up to 24 rows * 1024 floats (96KB)
    float* gs    = sm + 24 * 1024;     // 64 recurrent dot results
    float* gvbuf = gs + 64;            // 64 input-gate values
    float* cst   = gvbuf + 64;         // 16 cell states

    int b   = blockIdx.x;
    int dir = (b >= NBPD) ? 1 : 0;
    int lb  = dir ? b - NBPD : b;
    int u0  = (lb * HDIM) / NBPD;
    int u1  = ((lb + 1) * HDIM) / NBPD;
    int cnt = u1 - u0;                 // 13 or 14
    int nr  = cnt * 4;                 // 52 or 56
    int tid = threadIdx.x, lane = tid & 31, wid = tid >> 5;
    const float* Whh = dir ? Whh_r : Whh_f;

    // --- stage register rows (r = wid + 8q, q<QR; r<32<=nr always valid) ---
    ull wreg[QR][16];
#pragma unroll
    for (int q = 0; q < QR; q++) {
        int r = wid + 8 * q;
        int gate = r & 3, lu = r >> 2;
        const float* wrow = Whh + (size_t)(gate * HDIM + u0 + lu) * HDIM;
#pragma unroll
        for (int j = 0; j < 8; j++) {
            float4 w = __ldg((const float4*)(wrow + lane * 4 + j * 128));
            pk2(wreg[q][2 * j],     w.x, w.y);
            pk2(wreg[q][2 * j + 1], w.z, w.w);
        }
    }
    // --- stage smem rows (r = 32..nr-1) ---
    for (int r = 32; r < nr; r++) {
        int gate = r & 3, lu = r >> 2;
        const float4* src = (const float4*)(Whh + (size_t)(gate * HDIM + u0 + lu) * HDIM);
        ((float4*)(ws + (r - 32) * 1024))[tid] = __ldg(src + tid);
    }
    if (tid < cnt) cst[tid] = c0[dir * HDIM + u0 + tid];
    __syncthreads();

    const float* Gbase = g_G + (size_t)dir * TT * 4096u + (size_t)u0 * 4u;
    // prefetch g for step 0
    float gcur = 0.f, gnext = 0.f;
    {
        int tg0 = dir ? (TT - 1) : 0;
        if (tid < nr) gcur = __ldg(Gbase + (size_t)tg0 * 4096u + tid);
    }
    unsigned* cptr = &g_cnt[dir * TT];

    for (int s = 0; s < TT; s++) {
        // --- wait for state_s (producers flagged cptr[s-1]) ---
        if (s > 0) {
            if (tid == 0) {
                volatile unsigned* p = (volatile unsigned*)&cptr[s - 1];
                while (*p < (unsigned)NBPD) { }
                __threadfence();
            }
            __syncthreads();
        }

        // --- load h_s into packed registers (coalesced LDG, L1-safe: fresh addrs) ---
        const float* hrow = (s == 0)
            ? (g_h0 + dir * HDIM)
            : (g_lstm + (size_t)(dir ? (TT - s) : (s - 1)) * 2048u + dir * HDIM);
        ull hh[16];
#pragma unroll
        for (int j = 0; j < 8; j++) {
            float4 v = __ldg((const float4*)(hrow + lane * 4 + j * 128));
            pk2(hh[2 * j],     v.x, v.y);
            pk2(hh[2 * j + 1], v.z, v.w);
        }

        // publish g for activation; prefetch next step's g
        if (tid < nr) gvbuf[tid] = gcur;
        {
            int s1 = (s + 1 < TT) ? s + 1 : s;
            int tg1 = dir ? (TT - 1 - s1) : s1;
            if (tid < nr) gnext = __ldg(Gbase + (size_t)tg1 * 4096u + tid);
        }

        // --- recurrent dots ---
        float dots[7];
#pragma unroll
        for (int q = 0; q < QR; q++) {        // register rows
            ull acc = 0ull;
#pragma unroll
            for (int jj = 0; jj < 16; jj++) fma2(acc, wreg[q][jj], hh[jj], acc);
            float lo, hi; upk2(lo, hi, acc);
            dots[q] = lo + hi;
        }
#pragma unroll
        for (int q = QR; q < 7; q++) {        // smem rows
            int r = wid + 8 * q;
            float d = 0.f;
            if (r < nr) {
                const float* wr = ws + (r - 32) * 1024;
                ull acc = 0ull;
#pragma unroll
                for (int j = 0; j < 8; j++) {
                    float4 w = *(const float4*)(wr + lane * 4 + j * 128);
                    ull w0, w1;
                    pk2(w0, w.x, w.y); pk2(w1, w.z, w.w);
                    fma2(acc, w0, hh[2 * j], acc);
                    fma2(acc, w1, hh[2 * j + 1], acc);
                }
                float lo, hi; upk2(lo, hi, acc);
                d = lo + hi;
            }
            dots[q] = d;
        }
        // warp reductions, lane0 writes gs[r]
#pragma unroll
        for (int q = 0; q < 7; q++) {
            float v = dots[q];
#pragma unroll
            for (int off = 16; off; off >>= 1) v += __shfl_xor_sync(0xffffffffu, v, off);
            int r = wid + 8 * q;
            if (lane == 0 && r < nr) gs[r] = v;
        }
        __syncthreads();

        // --- activation + publish h ---
        if (tid < cnt) {
            float gi = gs[4 * tid + 0] + gvbuf[4 * tid + 0];
            float gf = gs[4 * tid + 1] + gvbuf[4 * tid + 1];
            float gg = gs[4 * tid + 2] + gvbuf[4 * tid + 2];
            float go = gs[4 * tid + 3] + gvbuf[4 * tid + 3];
            float iv = 1.f / (1.f + expf(-gi));
            float fv = 1.f / (1.f + expf(-gf));
            float gt = tanhf(gg);
            float ov = 1.f / (1.f + expf(-go));
            float cc = fv * cst[tid] + iv * gt;
            cst[tid] = cc;
            float h = ov * tanhf(cc);
            int trow = dir ? (TT - 1 - s) : s;
            g_lstm[(size_t)trow * 2048u + dir * HDIM + u0 + tid] = h;
        }
        __syncthreads();
        if (tid == 0) {
            __threadfence();                  // release our h stores (cumulative via bar)
            atomicAdd(&cptr[s], 1u);
        }
        gcur = gnext;
    }
}

// ---------------- feats = lstm_out @ W_tag^T + b_tag (deterministic reduction) ----------------
__global__ void __launch_bounds__(256) feats_kernel(
    const float* __restrict__ Wt, const float* __restrict__ bt)
{
    int t = blockIdx.x, tid = threadIdx.x;
    int lane = tid & 31, wid = tid >> 5;
    __shared__ float red2[KTAG][8];

    const float* row = g_lstm + (size_t)t * 2048u + tid * 8;
    float4 x0 = __ldg((const float4*)row);
    float4 x1 = __ldg((const float4*)(row + 4));

    for (int tag = 0; tag < KTAG; tag++) {
        const float* w = Wt + (size_t)tag * 2048u + tid * 8;
        float4 w0 = __ldg((const float4*)w);
        float4 w1 = __ldg((const float4*)(w + 4));
        float p = x0.x * w0.x + x0.y * w0.y + x0.z * w0.z + x0.w * w0.w
                + x1.x * w1.x + x1.y * w1.y + x1.z * w1.z + x1.w * w1.w;
#pragma unroll
        for (int off = 16; off; off >>= 1) p += __shfl_xor_sync(0xffffffffu, p, off);
        if (lane == 0) red2[tag][wid] = p;
    }
    __syncthreads();
    if (tid < KTAG) {
        float s = 0.f;
#pragma unroll
        for (int w2 = 0; w2 < 8; w2++) s += red2[tid][w2];
        g_feats[t * KTAG + tid] = s + __ldg(&bt[tid]);
    }
}

// ---------------- Viterbi DP + backtrack (single warp) ----------------
__global__ void viterbi_kernel(const float* __restrict__ trans, float* out, int out_size)
{
    extern __shared__ __align__(16) char vsm[];
    float* str  = (float*)vsm;               // 22*22 transitions
    float* fvs  = str + KTAG * KTAG;         // 22
    float* fbuf = fvs + KTAG;                // 2 * 64 * 22 feats double buffer
    unsigned char* bp = (unsigned char*)(fbuf + 2 * 64 * KTAG);  // 2048*22 backpointers

    int lane = threadIdx.x;
    for (int i = lane; i < KTAG * KTAG; i += 32) str[i] = __ldg(&trans[i]);
    if (lane < KTAG) fvs[lane] = (lane == STARTT) ? 0.f : NEGV;
    for (int i = lane; i < 64 * KTAG; i += 32) fbuf[i] = __ldg(&g_feats[i]);
    __syncwarp();

    const int CH = 64, NC = TT / CH;  // 32 chunks, 64*22 = 1408 = 44*32 floats each
    for (int c2 = 0; c2 < NC; c2++) {
        float pf[44];
        if (c2 + 1 < NC) {
#pragma unroll
            for (int i = 0; i < 44; i++)
                pf[i] = __ldg(&g_feats[(c2 + 1) * CH * KTAG + lane + i * 32]);
        }
        float* cur = fbuf + (c2 & 1) * CH * KTAG;
        for (int tt2 = 0; tt2 < CH; tt2++) {
            int t = c2 * CH + tt2;
            float nf = 0.f;
            if (lane < KTAG) {
                float m = -3.4e38f; int bi = 0;
                const float* trow = str + lane * KTAG;
                for (int p2 = 0; p2 < KTAG; p2++) {
                    float v = trow[p2] + fvs[p2];
                    if (v > m) { m = v; bi = p2; }   // strict > : first max (jnp.argmax)
                }
                nf = m + cur[tt2 * KTAG + lane];
                bp[t * KTAG + lane] = (unsigned char)bi;
            }
            __syncwarp();
            if (lane < KTAG) fvs[lane] = nf;
            __syncwarp();
        }
        if (c2 + 1 < NC) {
#pragma unroll
            for (int i = 0; i < 44; i++)
                fbuf[((c2 + 1) & 1) * CH * KTAG + lane + i * 32] = pf[i];
        }
        __syncwarp();
    }

    // terminal: max / first-index argmax of fvs + trans[END]
    float tv = (lane < KTAG) ? fvs[lane] + str[ENDT * KTAG + lane] : -3.4e38f;
    int ti = lane;
#pragma unroll
    for (int off = 16; off; off >>= 1) {
        float ov = __shfl_down_sync(0xffffffffu, tv, off);
        int   oi = __shfl_down_sync(0xffffffffu, ti, off);
        if (ov > tv || (ov == tv && oi < ti)) { tv = ov; ti = oi; }
    }
    if (lane == 0) {
        float* po = out;
        int n_path = 0;
        if (out_size >= TT + 1)      { out[0] = tv; po = out + 1; n_path = TT; }
        else if (out_size == TT)     { po = out;    n_path = TT; }
        else if (out_size >= 1)      { out[0] = tv; po = out + 1; n_path = out_size - 1; }
        int cur2 = ti;
        for (int t = TT - 1; t >= 0; t--) {
            if (t < n_path) po[t] = (float)cur2;
            cur2 = bp[t * KTAG + cur2];
        }
    }
}

// ---------------- launcher ----------------
extern "C" void kernel_launch(void* const* d_in, const int* in_sizes, int n_in,
                              void* d_out, int out_size)
{
    const float* seq    = (const float*)d_in[0];
    const float* h0     = (const float*)d_in[1];
    const float* c0     = (const float*)d_in[2];
    const float* Wih_f  = (const float*)d_in[3];
    const float* Whh_f  = (const float*)d_in[4];
    const float* bih_f  = (const float*)d_in[5];
    const float* bhh_f  = (const float*)d_in[6];
    const float* Wih_r  = (const float*)d_in[7];
    const float* Whh_r  = (const float*)d_in[8];
    const float* bih_r  = (const float*)d_in[9];
    const float* bhh_r  = (const float*)d_in[10];
    const float* W_tag  = (const float*)d_in[11];
    const float* b_tag  = (const float*)d_in[12];
    const float* transp = (const float*)d_in[13];

    static int attr_done = 0;
    const int RECUR_SMEM = (24 * 1024 + 64 + 64 + 16) * 4;         // ~98.8 KB
    const int VIT_SMEM   = KTAG * KTAG * 4 + KTAG * 4 + 2 * 64 * KTAG * 4 + TT * KTAG; // ~58.4 KB
    if (!attr_done) {
        cudaFuncSetAttribute(recur_kernel, cudaFuncAttributeMaxDynamicSharedMemorySize, RECUR_SMEM);
        cudaFuncSetAttribute(viterbi_kernel, cudaFuncAttributeMaxDynamicSharedMemorySize, VIT_SMEM);
        attr_done = 1;
    }

    init_kernel<<<4, 1024>>>(h0);

    dim3 ggrid(8192 / BN, 2048 / BM);
    gemm_kernel<<<ggrid, 256>>>(seq, Wih_f, Wih_r, bih_f, bhh_f, bih_r, bhh_r);

    recur_kernel<<<NBLK, 256, RECUR_SMEM>>>(Whh_f, Whh_r, c0);

    feats_kernel<<<TT, 256>>>(W_tag, b_tag);

    viterbi_kernel<<<1, 32, VIT_SMEM>>>(transp, (float*)d_out, out_size);
}